// round 7
// baseline (speedup 1.0000x reference)
#include <cuda_runtime.h>

// Shapes fixed by the problem: N=8192, D=64.
#define N_ROWS 8192
#define D_DIM  64

#define COLS4          (N_ROWS / 4)      // 2048 float4 per row
#define THREADS        256
#define STRIP4         256               // float4s per strip (1024 floats, 4KB/row) — R3 geometry
#define STRIPS         (COLS4 / STRIP4)  // 8 strips
#define ROWS_PER_BLOCK 32
#define GRID_Y         (N_ROWS / ROWS_PER_BLOCK)   // 256
#define NBLOCKS        (STRIPS * GRID_Y)           // 2048
#define GEMV_BLOCKS    32                // blocks 0..31 compute s1/s2 (256 rows each)

// Scratch + sync state (no cudaMalloc allowed). All counters net to zero
// at the end of every launch -> every call starts from identical state.
__device__ float g_s1[N_ROWS];
__device__ float g_s2[N_ROWS];
__device__ int   g_ready = 0;
__device__ int   g_done  = 0;

__device__ __forceinline__ float leaky(float e) {
    // e >= 0 ? e : 0.2*e  ==  max(e, 0.2*e) for all e
    return fmaxf(e, 0.2f * e);
}

__device__ __forceinline__ float4 row_vals(float s1, float4 s2) {
    float4 e;
    e.x = leaky(s1 + s2.x);
    e.y = leaky(s1 + s2.y);
    e.z = leaky(s1 + s2.z);
    e.w = leaky(s1 + s2.w);
    return e;
}

// Fused kernel.
// Phase A (blocks 0..31): thread-per-row GEMV of 256 rows each ->
//   g_s1 = Wh @ a[:64], g_s2 = Wh @ a[64:128]; then release g_ready.
// Phase B (all 2048 blocks): wait for g_ready==32, then stream a
//   1024-float column strip x 32 rows with coalesced 128-bit
//   evict-first stores (exact R3 geometry, measured 41.6us / 63% DRAM).
// Exit: stateless reset of counters by the last block to finish.
__global__ __launch_bounds__(THREADS) void fused_kernel(
        const float* __restrict__ Wh,
        const float* __restrict__ a,
        float4* __restrict__ out) {
    const int t   = threadIdx.x;
    const int bid = blockIdx.y * gridDim.x + blockIdx.x;

    // ---- Phase A: GEMV by the first 32 blocks ----
    if (bid < GEMV_BLOCKS) {
        const int row = bid * THREADS + t;
        const float4* w  = reinterpret_cast<const float4*>(Wh + (size_t)row * D_DIM);
        const float4* a1 = reinterpret_cast<const float4*>(a);
        const float4* a2 = reinterpret_cast<const float4*>(a + D_DIM);

        float acc1 = 0.f, acc2 = 0.f;
        #pragma unroll
        for (int i = 0; i < D_DIM / 4; i++) {
            float4 x = w[i];
            float4 y = a1[i];
            float4 z = a2[i];
            acc1 += x.x * y.x + x.y * y.y + x.z * y.z + x.w * y.w;
            acc2 += x.x * z.x + x.y * z.y + x.z * z.z + x.w * z.w;
        }
        g_s1[row] = acc1;
        g_s2[row] = acc2;

        __threadfence();           // make s1/s2 globally visible (all threads)
        __syncthreads();
        if (t == 0) atomicAdd(&g_ready, 1);
    }

    // ---- Wait for all GEMV chunks ----
    if (t == 0) {
        while (*((volatile int*)&g_ready) < GEMV_BLOCKS) __nanosleep(32);
        __threadfence();           // acquire
    }
    __syncthreads();

    // ---- Phase B: stream the output strip (R3 geometry) ----
    {
        const int c4   = blockIdx.x * STRIP4 + t;         // float4 column
        const int row0 = blockIdx.y * ROWS_PER_BLOCK;

        const float4 s2 = reinterpret_cast<const float4*>(g_s2)[c4];
        float4* dst = out + (size_t)row0 * COLS4 + c4;

        #pragma unroll 2
        for (int r = 0; r < ROWS_PER_BLOCK; r += 4) {
            float v0 = g_s1[row0 + r + 0];
            float v1 = g_s1[row0 + r + 1];
            float v2 = g_s1[row0 + r + 2];
            float v3 = g_s1[row0 + r + 3];

            __stcs(dst + 0 * (size_t)COLS4, row_vals(v0, s2));
            __stcs(dst + 1 * (size_t)COLS4, row_vals(v1, s2));
            __stcs(dst + 2 * (size_t)COLS4, row_vals(v2, s2));
            __stcs(dst + 3 * (size_t)COLS4, row_vals(v3, s2));
            dst += 4 * (size_t)COLS4;
        }
    }

    // ---- Stateless reset: last block to finish zeroes the counters ----
    __syncthreads();
    if (t == 0) {
        int prev = atomicAdd(&g_done, 1);
        if (prev == NBLOCKS - 1) {
            g_ready = 0;
            __threadfence();
            g_done = 0;            // state identical to launch-entry
        }
    }
}

extern "C" void kernel_launch(void* const* d_in, const int* in_sizes, int n_in,
                              void* d_out, int out_size) {
    const float* Wh = (const float*)d_in[0];
    const float* a  = (const float*)d_in[1];
    float4* out = (float4*)d_out;

    dim3 grid(STRIPS, GRID_Y);   // 8 x 256 = 2048 blocks
    fused_kernel<<<grid, THREADS>>>(Wh, a, out);
}

// round 8
// speedup vs baseline: 1.0391x; 1.0391x over previous
#include <cuda_runtime.h>

// Shapes fixed by the problem: N=8192, D=64.
#define N_ROWS 8192
#define D_DIM  64

#define COLS4          (N_ROWS / 4)      // 2048 float4 per row
#define THREADS        256
#define STRIP4         256               // float4s per strip (1024 floats, 4KB/row)
#define STRIPS         (COLS4 / STRIP4)  // 8 strips
#define ROWS_PER_BLOCK 32
#define GRID_Y         (N_ROWS / ROWS_PER_BLOCK)   // 256

// Scratch for GEMV results (no cudaMalloc allowed).
__device__ float g_s1[N_ROWS];
__device__ float g_s2[N_ROWS];

// Kernel 1: s1 = Wh @ a[:64], s2 = Wh @ a[64:128].
// One warp per row; each lane owns a float2 (64 elems / 32 lanes).
__global__ void gemv_kernel(const float* __restrict__ Wh,
                            const float* __restrict__ a) {
    const int warps_per_block = blockDim.x >> 5;
    const int row  = blockIdx.x * warps_per_block + (threadIdx.x >> 5);
    const int lane = threadIdx.x & 31;

    const float2 w  = reinterpret_cast<const float2*>(Wh + (size_t)row * D_DIM)[lane];
    const float2 a1 = reinterpret_cast<const float2*>(a)[lane];
    const float2 a2 = reinterpret_cast<const float2*>(a + D_DIM)[lane];

    float s1 = w.x * a1.x + w.y * a1.y;
    float s2 = w.x * a2.x + w.y * a2.y;

    #pragma unroll
    for (int off = 16; off > 0; off >>= 1) {
        s1 += __shfl_xor_sync(0xFFFFFFFFu, s1, off);
        s2 += __shfl_xor_sync(0xFFFFFFFFu, s2, off);
    }
    if (lane == 0) {
        g_s1[row] = s1;
        g_s2[row] = s2;
    }

    // Allow the dependent (outer) kernel's remaining blocks to launch;
    // its cudaGridDependencySynchronize still guarantees visibility of
    // the stores above.
    cudaTriggerProgrammaticLaunchCompletion();
}

__device__ __forceinline__ float leaky(float e) {
    // e >= 0 ? e : 0.2*e  ==  max(e, 0.2*e) for all e
    return fmaxf(e, 0.2f * e);
}

__device__ __forceinline__ float4 row_vals(float s1, float4 s2) {
    float4 e;
    e.x = leaky(s1 + s2.x);
    e.y = leaky(s1 + s2.y);
    e.z = leaky(s1 + s2.z);
    e.w = leaky(s1 + s2.w);
    return e;
}

// Kernel 2: out[i][j] = leaky(s1[i] + s2[j]).
// R3 geometry: 1024-float column strip x 32 rows per block, register-held s2,
// coalesced 128-bit evict-first stores, 4 independent stores in flight.
// Launched with PDL so its blocks ramp up while gemv drains.
__global__ __launch_bounds__(THREADS) void outer_kernel(float4* __restrict__ out) {
    // Prologue: pure index math, no dependence on gemv results.
    const int c4   = blockIdx.x * STRIP4 + threadIdx.x;  // float4 column
    const int row0 = blockIdx.y * ROWS_PER_BLOCK;
    float4* dst = out + (size_t)row0 * COLS4 + c4;

    // Wait for gemv's stores to be visible.
    cudaGridDependencySynchronize();

    const float4 s2 = reinterpret_cast<const float4*>(g_s2)[c4];

    #pragma unroll 2
    for (int r = 0; r < ROWS_PER_BLOCK; r += 4) {
        float v0 = g_s1[row0 + r + 0];
        float v1 = g_s1[row0 + r + 1];
        float v2 = g_s1[row0 + r + 2];
        float v3 = g_s1[row0 + r + 3];

        __stcs(dst + 0 * (size_t)COLS4, row_vals(v0, s2));
        __stcs(dst + 1 * (size_t)COLS4, row_vals(v1, s2));
        __stcs(dst + 2 * (size_t)COLS4, row_vals(v2, s2));
        __stcs(dst + 3 * (size_t)COLS4, row_vals(v3, s2));
        dst += 4 * (size_t)COLS4;
    }
}

extern "C" void kernel_launch(void* const* d_in, const int* in_sizes, int n_in,
                              void* d_out, int out_size) {
    const float* Wh = (const float*)d_in[0];
    const float* a  = (const float*)d_in[1];
    float4* out = (float4*)d_out;

    // Kernel 1: 8192 warps -> 8 warps/block, 1024 blocks (default stream).
    gemv_kernel<<<N_ROWS / 8, 256>>>(Wh, a);

    // Kernel 2 with programmatic dependent launch: blocks may launch while
    // gemv drains; they grid-sync before consuming s1/s2.
    cudaLaunchConfig_t cfg = {};
    cfg.gridDim  = dim3(STRIPS, GRID_Y);   // 8 x 256 = 2048 blocks
    cfg.blockDim = dim3(THREADS);
    cfg.dynamicSmemBytes = 0;
    cfg.stream = 0;  // same (capture) stream as the legacy launch above

    cudaLaunchAttribute attr[1];
    attr[0].id = cudaLaunchAttributeProgrammaticStreamSerialization;
    attr[0].val.programmaticStreamSerializationAllowed = 1;
    cfg.attrs = attr;
    cfg.numAttrs = 1;

    cudaLaunchKernelEx(&cfg, outer_kernel, out);
}